// round 14
// baseline (speedup 1.0000x reference)
#include <cuda_runtime.h>
#include <math.h>

#define Bv 1024
#define Sv 2048
#define Dv 64
#define Hv 4
#define HDv 16

#define NSTAGE 12      // smem ring stages per warp
#define LOOKAHEAD 8    // chunks in flight

__device__ __forceinline__ void cp_async16(void* smem_dst, const void* gsrc) {
    unsigned sd = (unsigned)__cvta_generic_to_shared(smem_dst);
    asm volatile("cp.async.cg.shared.global [%0], [%1], 16;\n"
                 :: "r"(sd), "l"(gsrc) : "memory");
}
#define CP_COMMIT() asm volatile("cp.async.commit_group;\n" ::: "memory")
#define CP_WAIT6()  asm volatile("cp.async.wait_group 6;\n" ::: "memory")
#define CP_WAIT0()  asm volatile("cp.async.wait_group 0;\n" ::: "memory")

// ---- packed f32x2 helpers (sm_103a paired-FP32 pipe) ----
typedef unsigned long long u64t;
__device__ __forceinline__ u64t pk2(float a, float b) {
    u64t r; asm("mov.b64 %0, {%1, %2};" : "=l"(r) : "f"(a), "f"(b)); return r;
}
__device__ __forceinline__ void unpk2(float& a, float& b, u64t p) {
    asm("mov.b64 {%0, %1}, %2;" : "=f"(a), "=f"(b) : "l"(p));
}
__device__ __forceinline__ u64t mul2(u64t a, u64t b) {
    u64t r; asm("mul.rn.f32x2 %0, %1, %2;" : "=l"(r) : "l"(a), "l"(b)); return r;
}
__device__ __forceinline__ void fma2(u64t& d, u64t a, u64t b) {
    asm("fma.rn.f32x2 %0, %1, %2, %0;" : "+l"(d) : "l"(a), "l"(b));
}

// ---- bf16x2 shuffle packing (R12, verified) ----
__device__ __forceinline__ unsigned bpk(float hi, float lo) {
    unsigned r; asm("cvt.rn.bf16x2.f32 %0, %1, %2;" : "=r"(r) : "f"(hi), "f"(lo));
    return r;
}
__device__ __forceinline__ float blo(unsigned p) { return __uint_as_float(p << 16); }
__device__ __forceinline__ float bhi(unsigned p) { return __uint_as_float(p & 0xffff0000u); }

#define LOG2E 1.4426950408889634f

// ---------------------------------------------------------------------------
// FUSED kernel (R13): the whole problem is per-batch separable, so one CTA
// does everything for its batch — attention pass (R12's verified loop),
// epilogue matvecs (h, write_value kept in smem), address logits + softmax
// (w_a2 read from L2; e[] in the dyn buffer), then the write-back stream.
// This removes the artificial k1->k2->k3 serialization: CTAs in different
// phases overlap latency-bound (attention) and DRAM-bound (stream) work.
// ---------------------------------------------------------------------------
__global__ __launch_bounds__(256, 2) void fused_actformer(
    const float* __restrict__ query, const float* __restrict__ sp,
    const float* __restrict__ wq, const float* __restrict__ wk,
    const float* __restrict__ wv, const float* __restrict__ bq,
    const float* __restrict__ bk, const float* __restrict__ bv,
    const float* __restrict__ wo, const float* __restrict__ bo,
    const float* __restrict__ w_write, const float* __restrict__ b_write,
    const float* __restrict__ w_a1, const float* __restrict__ b_a1,
    const float* __restrict__ w_a2, const float* __restrict__ b_a2,
    float* __restrict__ outp)
{
    extern __shared__ float dyn[];   // 8 warps * 12 stages * 272 floats (104.4KB)
                                     // aliased: partial-combine buf, then e[2048]
    __shared__ float s_q[Dv];
    __shared__ float s_qv[Dv];
    __shared__ float s_qk[Hv * Dv];
    __shared__ float s_c[Hv];
    __shared__ float s_pl[32 * Hv];
    __shared__ float s_wvec[Hv * Dv];
    __shared__ float s_ctx[Dv];
    __shared__ float s_val[Dv];
    __shared__ float s_h[128];       // relu hidden
    __shared__ float s_wv[Dv];       // write_value
    __shared__ float s_den;

    const int b = blockIdx.x;
    const int t = threadIdx.x;
    const int warp = t >> 5, lane = t & 31;
    const int g = lane >> 3, sub = lane & 7;
    const float* spb = sp + (size_t)b * Sv * Dv;

    float* wbase = dyn + warp * (NSTAGE * 272);     // this warp's private ring
    float* lbase = wbase + g * 68 + sub * 4;        // lane's write slot (per stage)
    const float* src0 = spb + ((size_t)warp * 256 + g) * 64 + sub * 4;

    // ================= Phase A: attention pass (R12 verbatim) =================
#pragma unroll
    for (int c = 0; c < LOOKAHEAD; c++) {
        float* dst = lbase + c * 272;
        const float* src = src0 + (size_t)c * 256;
        cp_async16(dst, src);
        cp_async16(dst + 32, src + 32);
        CP_COMMIT();
    }

    if (t < Dv) s_q[t] = query[(size_t)b * Dv + t];
    __syncthreads();
    if (t < Dv) {
        float acc = bq[t];
        const float* wr = wq + t * Dv;
#pragma unroll
        for (int j = 0; j < Dv; j++) acc += __ldg(wr + j) * s_q[j];
        s_qv[t] = acc;
    }
    __syncthreads();

    {
        const int h = t >> 6, j = t & 63;
        float acc = 0.f;
#pragma unroll
        for (int tt = 0; tt < HDv; tt++)
            acc += s_qv[h * HDv + tt] * __ldg(&wk[(h * HDv + tt) * Dv + j]);
        s_qk[h * Dv + j] = 0.25f * acc;
        if (t < Hv) {
            float c = 0.f;
#pragma unroll
            for (int tt = 0; tt < HDv; tt++) c += s_qv[t * HDv + tt] * __ldg(&bk[t * HDv + tt]);
            s_c[t] = 0.25f * c;
        }
    }
    __syncthreads();

    u64t qk2[Hv][4];
#pragma unroll
    for (int h = 0; h < Hv; h++) {
        float r[8];
#pragma unroll
        for (int k = 0; k < 8; k++) {
            int d = (k < 4) ? (4 * sub + k) : (32 + 4 * sub + k - 4);
            r[k] = s_qk[h * Dv + d];
        }
#pragma unroll
        for (int kk = 0; kk < 4; kk++) qk2[h][kk] = pk2(r[2 * kk], r[2 * kk + 1]);
    }
    const int base = sub & 3;
    const float cprem = s_c[base] * LOG2E;
    const bool b0 = (sub & 1) != 0;
    const bool b1 = (sub & 2) != 0;

    u64t u2[Hv][4];
    float ls[Hv];
#pragma unroll
    for (int j = 0; j < Hv; j++) {
        ls[j] = 0.f;
#pragma unroll
        for (int kk = 0; kk < 4; kk++) u2[j][kk] = 0ull;
    }

    int st = 0;
    int nst = LOOKAHEAD;
#pragma unroll 1
    for (int c = 0; c < 64; c += 2) {
        CP_WAIT6();

        if (c + 8 < 64) {
            cp_async16(lbase + nst * 272, src0 + (size_t)(c + 8) * 256);
            cp_async16(lbase + nst * 272 + 32, src0 + (size_t)(c + 8) * 256 + 32);
        }
        CP_COMMIT();
        if (c + 9 < 64) {
            cp_async16(lbase + (nst + 1) * 272, src0 + (size_t)(c + 9) * 256);
            cp_async16(lbase + (nst + 1) * 272 + 32, src0 + (size_t)(c + 9) * 256 + 32);
        }
        CP_COMMIT();

        u64t XP[2][4];
#pragma unroll
        for (int j = 0; j < 2; j++) {
            const float4* tp = (const float4*)(wbase + (st + j) * 272);
            float4 a0 = tp[g * 17 + sub];
            float4 a1 = tp[g * 17 + 8 + sub];
            XP[j][0] = pk2(a0.x, a0.y); XP[j][1] = pk2(a0.z, a0.w);
            XP[j][2] = pk2(a1.x, a1.y); XP[j][3] = pk2(a1.z, a1.w);
        }

        float V[2][Hv];
#pragma unroll
        for (int j = 0; j < 2; j++)
#pragma unroll
            for (int h = 0; h < Hv; h++) {
                u64t acc = mul2(qk2[h][0], XP[j][0]);
                fma2(acc, qk2[h][1], XP[j][1]);
                fma2(acc, qk2[h][2], XP[j][2]);
                fma2(acc, qk2[h][3], XP[j][3]);
                float lo, hi; unpk2(lo, hi, acc);
                V[j][h] = lo + hi;
            }

        float a0s[2], a1s[2];
        {
            float s0[2], s1[2];
#pragma unroll
            for (int j = 0; j < 2; j++) {
                s0[j] = b1 ? V[j][0] : V[j][2];
                s1[j] = b1 ? V[j][1] : V[j][3];
            }
            unsigned P0 = bpk(s0[1], s0[0]);
            unsigned P1 = bpk(s1[1], s1[0]);
            unsigned R0 = __shfl_xor_sync(0xffffffffu, P0, 2);
            unsigned R1 = __shfl_xor_sync(0xffffffffu, P1, 2);
            a0s[0] = (b1 ? V[0][2] : V[0][0]) + blo(R0);
            a0s[1] = (b1 ? V[1][2] : V[1][0]) + bhi(R0);
            a1s[0] = (b1 ? V[0][3] : V[0][1]) + blo(R1);
            a1s[1] = (b1 ? V[1][3] : V[1][1]) + bhi(R1);
        }
        float S[2];
        {
            float s2[2];
#pragma unroll
            for (int j = 0; j < 2; j++) s2[j] = b0 ? a0s[j] : a1s[j];
            unsigned P2 = bpk(s2[1], s2[0]);
            unsigned R2 = __shfl_xor_sync(0xffffffffu, P2, 1);
            S[0] = (b0 ? a1s[0] : a0s[0]) + blo(R2);
            S[1] = (b0 ? a1s[1] : a0s[1]) + bhi(R2);
            unsigned P3 = bpk(S[1], S[0]);
            unsigned R3 = __shfl_xor_sync(0xffffffffu, P3, 4);
            S[0] += blo(R3);
            S[1] += bhi(R3);
        }

        float Q[2][4];
        {
            float q0[2];
#pragma unroll
            for (int j = 0; j < 2; j++) q0[j] = exp2f(__fmaf_rn(S[j], LOG2E, cprem));
            unsigned Q0p = bpk(q0[1], q0[0]);
            unsigned Q1p = __shfl_xor_sync(0xffffffffu, Q0p, 1);
            unsigned Q2p = __shfl_xor_sync(0xffffffffu, Q0p, 2);
            unsigned Q3p = __shfl_xor_sync(0xffffffffu, Q1p, 2);
            Q[0][0] = q0[0];     Q[1][0] = q0[1];
            Q[0][1] = blo(Q1p);  Q[1][1] = bhi(Q1p);
            Q[0][2] = blo(Q2p);  Q[1][2] = bhi(Q2p);
            Q[0][3] = blo(Q3p);  Q[1][3] = bhi(Q3p);
        }

#pragma unroll
        for (int j = 0; j < 2; j++) {
#pragma unroll
            for (int hh = 0; hh < Hv; hh++) {
                ls[hh] += Q[j][hh];
                u64t qq = pk2(Q[j][hh], Q[j][hh]);
                fma2(u2[hh][0], qq, XP[j][0]);
                fma2(u2[hh][1], qq, XP[j][1]);
                fma2(u2[hh][2], qq, XP[j][2]);
                fma2(u2[hh][3], qq, XP[j][3]);
            }
        }

        st += 2;  if (st >= NSTAGE) st -= NSTAGE;
        nst += 2; if (nst >= NSTAGE) nst -= NSTAGE;
    }
    CP_WAIT0();
    __syncthreads();

    // ---- combine 32 group partials (dyn aliased; 8192 floats) ----
    float* s_part = dyn;
    const int pg = warp * 4 + g;
    if (sub == 0) {
#pragma unroll
        for (int j = 0; j < Hv; j++) s_pl[pg * 4 + j] = ls[j];
    }
#pragma unroll
    for (int j = 0; j < Hv; j++) {
        const int h = base ^ j;
#pragma unroll
        for (int kk = 0; kk < 4; kk++) {
            float lo, hi; unpk2(lo, hi, u2[j][kk]);
            int k0 = 2 * kk, k1 = 2 * kk + 1;
            int d0 = (k0 < 4) ? (4 * sub + k0) : (32 + 4 * sub + k0 - 4);
            int d1 = (k1 < 4) ? (4 * sub + k1) : (32 + 4 * sub + k1 - 4);
            s_part[(pg * 4 + h) * 64 + d0] = lo;
            s_part[(pg * 4 + h) * 64 + d1] = hi;
        }
    }
    __syncthreads();
    {
        const int h = t >> 6, d = t & 63;
        float U = 0.f;
#pragma unroll
        for (int p = 0; p < 32; p++) U += s_part[(p * 4 + h) * 64 + d];
        float L = 0.f;
#pragma unroll
        for (int p = 0; p < 32; p++) L += s_pl[p * 4 + h];
        s_wvec[h * 64 + d] = U / L;
    }
    __syncthreads();

    // ================= Phase B: epilogue matvec chain =================
    if (t < Dv) {
        float acc = bv[t];
        const int h = t >> 4;
        const float* wr = wv + t * Dv;
#pragma unroll
        for (int j = 0; j < Dv; j++) acc += __ldg(wr + j) * s_wvec[h * 64 + j];
        s_ctx[t] = acc;
    }
    __syncthreads();
    if (t < Dv) {
        float acc = bo[t];
        const float* wr = wo + t * Dv;
#pragma unroll
        for (int j = 0; j < Dv; j++) acc += __ldg(wr + j) * s_ctx[j];
        s_val[t] = acc;
    }
    __syncthreads();
    if (t < 128) {
        float acc = b_a1[t];
        const float* wr = w_a1 + t * Dv;
#pragma unroll
        for (int j = 0; j < Dv; j++) acc += __ldg(wr + j) * s_val[j];
        s_h[t] = fmaxf(acc, 0.f);
    }
    if (t >= 128 && t < 128 + Dv) {
        const int o = t - 128;
        float acc = b_write[o];
        const float* wr = w_write + o * Dv;
#pragma unroll
        for (int j = 0; j < Dv; j++) acc += __ldg(wr + j) * s_val[j];
        s_wv[o] = acc;
    }
    if (t == 255) s_den = 0.f;
    __syncthreads();

    // ================= Phase C: address logits + softmax =================
    // e[s] for s = t + 256r, r=0..7; dot(h[128], w_a2[s]) + b_a2[s].
    // w_a2 is 1MB, L2-resident across the grid. e[] lands in dyn[0..2047].
    {
        float acc[8];
#pragma unroll
        for (int r = 0; r < 8; r++) acc[r] = 0.f;
        const float4* h4 = (const float4*)s_h;
        const float4* w4 = (const float4*)w_a2;
#pragma unroll 1
        for (int k8 = 0; k8 < 16; k8++) {
            float4 ha = h4[2 * k8];
            float4 hb = h4[2 * k8 + 1];
#pragma unroll
            for (int r = 0; r < 8; r++) {
                const int s = t + 256 * r;
                float4 wa = __ldg(w4 + (size_t)s * 32 + 2 * k8);
                float4 wb = __ldg(w4 + (size_t)s * 32 + 2 * k8 + 1);
                acc[r] += wa.x * ha.x + wa.y * ha.y + wa.z * ha.z + wa.w * ha.w +
                          wb.x * hb.x + wb.y * hb.y + wb.z * hb.z + wb.w * hb.w;
            }
        }
        float psum = 0.f;
#pragma unroll
        for (int r = 0; r < 8; r++) {
            const int s = t + 256 * r;
            float e = __expf(acc[r] + b_a2[s]);   // logits small -> safe w/o max-sub
            dyn[s] = e;
            psum += e;
        }
#pragma unroll
        for (int off = 16; off; off >>= 1)
            psum += __shfl_xor_sync(0xffffffffu, psum, off);
        if (lane == 0) atomicAdd(&s_den, psum);
    }
    __syncthreads();
    const float inv = 1.f / s_den;

    // ================= Phase D: write-back stream =================
    // out[b,s,:] = sp + (write_value - sp) * a[s]; 512KB read + 512KB write.
    {
        const float4* sp4 = (const float4*)spb;
        float4* out4 = (float4*)(outp + (size_t)b * Sv * Dv);
        const float4 w = ((const float4*)s_wv)[t & 15];
        const int rbase = t >> 4;
#pragma unroll 1
        for (int j = 0; j < 128; j += 4) {
            float a0 = dyn[rbase + (j + 0) * 16] * inv;
            float a1 = dyn[rbase + (j + 1) * 16] * inv;
            float a2 = dyn[rbase + (j + 2) * 16] * inv;
            float a3 = dyn[rbase + (j + 3) * 16] * inv;
            float4 x0 = __ldcs(sp4 + t + (size_t)(j + 0) * 256);
            float4 x1 = __ldcs(sp4 + t + (size_t)(j + 1) * 256);
            float4 x2 = __ldcs(sp4 + t + (size_t)(j + 2) * 256);
            float4 x3 = __ldcs(sp4 + t + (size_t)(j + 3) * 256);
            float4 o0, o1, o2, o3;
            o0.x = x0.x + (w.x - x0.x) * a0; o0.y = x0.y + (w.y - x0.y) * a0;
            o0.z = x0.z + (w.z - x0.z) * a0; o0.w = x0.w + (w.w - x0.w) * a0;
            o1.x = x1.x + (w.x - x1.x) * a1; o1.y = x1.y + (w.y - x1.y) * a1;
            o1.z = x1.z + (w.z - x1.z) * a1; o1.w = x1.w + (w.w - x1.w) * a1;
            o2.x = x2.x + (w.x - x2.x) * a2; o2.y = x2.y + (w.y - x2.y) * a2;
            o2.z = x2.z + (w.z - x2.z) * a2; o2.w = x2.w + (w.w - x2.w) * a2;
            o3.x = x3.x + (w.x - x3.x) * a3; o3.y = x3.y + (w.y - x3.y) * a3;
            o3.z = x3.z + (w.z - x3.z) * a3; o3.w = x3.w + (w.w - x3.w) * a3;
            __stcs(out4 + t + (size_t)(j + 0) * 256, o0);
            __stcs(out4 + t + (size_t)(j + 1) * 256, o1);
            __stcs(out4 + t + (size_t)(j + 2) * 256, o2);
            __stcs(out4 + t + (size_t)(j + 3) * 256, o3);
        }
    }
}

extern "C" void kernel_launch(void* const* d_in, const int* in_sizes, int n_in,
                              void* d_out, int out_size)
{
    (void)in_sizes; (void)n_in; (void)out_size;
    const float* query   = (const float*)d_in[0];
    const float* sp      = (const float*)d_in[1];
    const float* wq      = (const float*)d_in[2];
    const float* wk      = (const float*)d_in[3];
    const float* wv      = (const float*)d_in[4];
    const float* bq      = (const float*)d_in[5];
    const float* bk      = (const float*)d_in[6];
    const float* bv      = (const float*)d_in[7];
    const float* wo      = (const float*)d_in[8];
    const float* bo      = (const float*)d_in[9];
    const float* w_write = (const float*)d_in[10];
    const float* b_write = (const float*)d_in[11];
    const float* w_a1    = (const float*)d_in[12];
    const float* b_a1    = (const float*)d_in[13];
    const float* w_a2    = (const float*)d_in[14];
    const float* b_a2    = (const float*)d_in[15];
    float* out = (float*)d_out;

    const int dyn_bytes = 8 * NSTAGE * 272 * (int)sizeof(float);   // 104448
    cudaFuncSetAttribute(fused_actformer, cudaFuncAttributeMaxDynamicSharedMemorySize,
                         dyn_bytes);

    fused_actformer<<<Bv, 256, dyn_bytes>>>(query, sp, wq, wk, wv, bq, bk, bv,
                                            wo, bo, w_write, b_write,
                                            w_a1, b_a1, w_a2, b_a2, out);
}

// round 15
// speedup vs baseline: 1.9049x; 1.9049x over previous
#include <cuda_runtime.h>
#include <math.h>

#define Bv 1024
#define Sv 2048
#define Dv 64
#define Hv 4
#define HDv 16

#define NSTAGE 12      // smem ring stages per warp
#define LOOKAHEAD 8    // chunks in flight

// Scratch (no cudaMalloc allowed) — static device globals.
__device__ float g_hbuf[Bv * 128];        // relu(value @ w_a1.T + b_a1)
__device__ float g_wvbuf[Bv * Dv];        // write_value per batch
__device__ float g_ebuf[(size_t)Bv * Sv]; // UNNORMALIZED exp(logits)
__device__ float g_psum[Bv * 8];          // per-(batch, s-tile) partial exp-sums
__device__ float g_invd[Bv];              // 1/sum(exp) per batch

__device__ __forceinline__ void cp_async16(void* smem_dst, const void* gsrc) {
    unsigned sd = (unsigned)__cvta_generic_to_shared(smem_dst);
    asm volatile("cp.async.cg.shared.global [%0], [%1], 16;\n"
                 :: "r"(sd), "l"(gsrc) : "memory");
}
#define CP_COMMIT() asm volatile("cp.async.commit_group;\n" ::: "memory")
#define CP_WAIT6()  asm volatile("cp.async.wait_group 6;\n" ::: "memory")
#define CP_WAIT0()  asm volatile("cp.async.wait_group 0;\n" ::: "memory")

// ---- packed f32x2 helpers (sm_103a paired-FP32 pipe) ----
typedef unsigned long long u64t;
__device__ __forceinline__ u64t pk2(float a, float b) {
    u64t r; asm("mov.b64 %0, {%1, %2};" : "=l"(r) : "f"(a), "f"(b)); return r;
}
__device__ __forceinline__ void unpk2(float& a, float& b, u64t p) {
    asm("mov.b64 {%0, %1}, %2;" : "=f"(a), "=f"(b) : "l"(p));
}
__device__ __forceinline__ u64t mul2(u64t a, u64t b) {
    u64t r; asm("mul.rn.f32x2 %0, %1, %2;" : "=l"(r) : "l"(a), "l"(b)); return r;
}
__device__ __forceinline__ void fma2(u64t& d, u64t a, u64t b) {
    asm("fma.rn.f32x2 %0, %1, %2, %0;" : "+l"(d) : "l"(a), "l"(b));
}

// ---- bf16x2 shuffle packing (R12, verified) ----
__device__ __forceinline__ unsigned bpk(float hi, float lo) {
    unsigned r; asm("cvt.rn.bf16x2.f32 %0, %1, %2;" : "=r"(r) : "f"(hi), "f"(lo));
    return r;
}
__device__ __forceinline__ float blo(unsigned p) { return __uint_as_float(p << 16); }
__device__ __forceinline__ float bhi(unsigned p) { return __uint_as_float(p & 0xffff0000u); }

#define LOG2E 1.4426950408889634f

// ---------------------------------------------------------------------------
// K1 (R12 champion, verbatim): per-warp cp.async ring, unroll-2 interleaved
// chains, bf16x2-packed shuffle reduction. 167.8us measured.
// ---------------------------------------------------------------------------
__global__ __launch_bounds__(256, 2) void k1_attn(
    const float* __restrict__ query, const float* __restrict__ sp,
    const float* __restrict__ wq, const float* __restrict__ wk,
    const float* __restrict__ wv, const float* __restrict__ bq,
    const float* __restrict__ bk, const float* __restrict__ bv,
    const float* __restrict__ wo, const float* __restrict__ bo,
    const float* __restrict__ w_write, const float* __restrict__ b_write,
    const float* __restrict__ w_a1, const float* __restrict__ b_a1)
{
    extern __shared__ float dyn[];   // 8 warps * 12 stages * 272 floats (104.4KB)
    __shared__ float s_q[Dv];
    __shared__ float s_qv[Dv];
    __shared__ float s_qk[Hv * Dv];
    __shared__ float s_c[Hv];
    __shared__ float s_pl[32 * Hv];
    __shared__ float s_wvec[Hv * Dv];
    __shared__ float s_ctx[Dv];
    __shared__ float s_val[Dv];

    const int b = blockIdx.x;
    const int t = threadIdx.x;
    const int warp = t >> 5, lane = t & 31;
    const int g = lane >> 3, sub = lane & 7;
    const float* spb = sp + (size_t)b * Sv * Dv;

    float* wbase = dyn + warp * (NSTAGE * 272);     // this warp's private ring
    float* lbase = wbase + g * 68 + sub * 4;        // lane's write slot (per stage)
    const float* src0 = spb + ((size_t)warp * 256 + g) * 64 + sub * 4;

#pragma unroll
    for (int c = 0; c < LOOKAHEAD; c++) {
        float* dst = lbase + c * 272;
        const float* src = src0 + (size_t)c * 256;
        cp_async16(dst, src);
        cp_async16(dst + 32, src + 32);
        CP_COMMIT();
    }

    if (t < Dv) s_q[t] = query[(size_t)b * Dv + t];
    __syncthreads();
    if (t < Dv) {
        float acc = bq[t];
        const float* wr = wq + t * Dv;
#pragma unroll
        for (int j = 0; j < Dv; j++) acc += __ldg(wr + j) * s_q[j];
        s_qv[t] = acc;
    }
    __syncthreads();

    {
        const int h = t >> 6, j = t & 63;
        float acc = 0.f;
#pragma unroll
        for (int tt = 0; tt < HDv; tt++)
            acc += s_qv[h * HDv + tt] * __ldg(&wk[(h * HDv + tt) * Dv + j]);
        s_qk[h * Dv + j] = 0.25f * acc;
        if (t < Hv) {
            float c = 0.f;
#pragma unroll
            for (int tt = 0; tt < HDv; tt++) c += s_qv[t * HDv + tt] * __ldg(&bk[t * HDv + tt]);
            s_c[t] = 0.25f * c;
        }
    }
    __syncthreads();

    u64t qk2[Hv][4];
#pragma unroll
    for (int h = 0; h < Hv; h++) {
        float r[8];
#pragma unroll
        for (int k = 0; k < 8; k++) {
            int d = (k < 4) ? (4 * sub + k) : (32 + 4 * sub + k - 4);
            r[k] = s_qk[h * Dv + d];
        }
#pragma unroll
        for (int kk = 0; kk < 4; kk++) qk2[h][kk] = pk2(r[2 * kk], r[2 * kk + 1]);
    }
    const int base = sub & 3;
    const float cprem = s_c[base] * LOG2E;
    const bool b0 = (sub & 1) != 0;
    const bool b1 = (sub & 2) != 0;

    u64t u2[Hv][4];
    float ls[Hv];
#pragma unroll
    for (int j = 0; j < Hv; j++) {
        ls[j] = 0.f;
#pragma unroll
        for (int kk = 0; kk < 4; kk++) u2[j][kk] = 0ull;
    }

    int st = 0;
    int nst = LOOKAHEAD;
#pragma unroll 1
    for (int c = 0; c < 64; c += 2) {
        CP_WAIT6();

        if (c + 8 < 64) {
            cp_async16(lbase + nst * 272, src0 + (size_t)(c + 8) * 256);
            cp_async16(lbase + nst * 272 + 32, src0 + (size_t)(c + 8) * 256 + 32);
        }
        CP_COMMIT();
        if (c + 9 < 64) {
            cp_async16(lbase + (nst + 1) * 272, src0 + (size_t)(c + 9) * 256);
            cp_async16(lbase + (nst + 1) * 272 + 32, src0 + (size_t)(c + 9) * 256 + 32);
        }
        CP_COMMIT();

        u64t XP[2][4];
#pragma unroll
        for (int j = 0; j < 2; j++) {
            const float4* tp = (const float4*)(wbase + (st + j) * 272);
            float4 a0 = tp[g * 17 + sub];
            float4 a1 = tp[g * 17 + 8 + sub];
            XP[j][0] = pk2(a0.x, a0.y); XP[j][1] = pk2(a0.z, a0.w);
            XP[j][2] = pk2(a1.x, a1.y); XP[j][3] = pk2(a1.z, a1.w);
        }

        float V[2][Hv];
#pragma unroll
        for (int j = 0; j < 2; j++)
#pragma unroll
            for (int h = 0; h < Hv; h++) {
                u64t acc = mul2(qk2[h][0], XP[j][0]);
                fma2(acc, qk2[h][1], XP[j][1]);
                fma2(acc, qk2[h][2], XP[j][2]);
                fma2(acc, qk2[h][3], XP[j][3]);
                float lo, hi; unpk2(lo, hi, acc);
                V[j][h] = lo + hi;
            }

        float a0s[2], a1s[2];
        {
            float s0[2], s1[2];
#pragma unroll
            for (int j = 0; j < 2; j++) {
                s0[j] = b1 ? V[j][0] : V[j][2];
                s1[j] = b1 ? V[j][1] : V[j][3];
            }
            unsigned P0 = bpk(s0[1], s0[0]);
            unsigned P1 = bpk(s1[1], s1[0]);
            unsigned R0 = __shfl_xor_sync(0xffffffffu, P0, 2);
            unsigned R1 = __shfl_xor_sync(0xffffffffu, P1, 2);
            a0s[0] = (b1 ? V[0][2] : V[0][0]) + blo(R0);
            a0s[1] = (b1 ? V[1][2] : V[1][0]) + bhi(R0);
            a1s[0] = (b1 ? V[0][3] : V[0][1]) + blo(R1);
            a1s[1] = (b1 ? V[1][3] : V[1][1]) + bhi(R1);
        }
        float S[2];
        {
            float s2[2];
#pragma unroll
            for (int j = 0; j < 2; j++) s2[j] = b0 ? a0s[j] : a1s[j];
            unsigned P2 = bpk(s2[1], s2[0]);
            unsigned R2 = __shfl_xor_sync(0xffffffffu, P2, 1);
            S[0] = (b0 ? a1s[0] : a0s[0]) + blo(R2);
            S[1] = (b0 ? a1s[1] : a0s[1]) + bhi(R2);
            unsigned P3 = bpk(S[1], S[0]);
            unsigned R3 = __shfl_xor_sync(0xffffffffu, P3, 4);
            S[0] += blo(R3);
            S[1] += bhi(R3);
        }

        float Q[2][4];
        {
            float q0[2];
#pragma unroll
            for (int j = 0; j < 2; j++) q0[j] = exp2f(__fmaf_rn(S[j], LOG2E, cprem));
            unsigned Q0p = bpk(q0[1], q0[0]);
            unsigned Q1p = __shfl_xor_sync(0xffffffffu, Q0p, 1);
            unsigned Q2p = __shfl_xor_sync(0xffffffffu, Q0p, 2);
            unsigned Q3p = __shfl_xor_sync(0xffffffffu, Q1p, 2);
            Q[0][0] = q0[0];     Q[1][0] = q0[1];
            Q[0][1] = blo(Q1p);  Q[1][1] = bhi(Q1p);
            Q[0][2] = blo(Q2p);  Q[1][2] = bhi(Q2p);
            Q[0][3] = blo(Q3p);  Q[1][3] = bhi(Q3p);
        }

#pragma unroll
        for (int j = 0; j < 2; j++) {
#pragma unroll
            for (int hh = 0; hh < Hv; hh++) {
                ls[hh] += Q[j][hh];
                u64t qq = pk2(Q[j][hh], Q[j][hh]);
                fma2(u2[hh][0], qq, XP[j][0]);
                fma2(u2[hh][1], qq, XP[j][1]);
                fma2(u2[hh][2], qq, XP[j][2]);
                fma2(u2[hh][3], qq, XP[j][3]);
            }
        }

        st += 2;  if (st >= NSTAGE) st -= NSTAGE;
        nst += 2; if (nst >= NSTAGE) nst -= NSTAGE;
    }
    CP_WAIT0();
    __syncthreads();

    float* s_part = dyn;
    const int pg = warp * 4 + g;
    if (sub == 0) {
#pragma unroll
        for (int j = 0; j < Hv; j++) s_pl[pg * 4 + j] = ls[j];
    }
#pragma unroll
    for (int j = 0; j < Hv; j++) {
        const int h = base ^ j;
#pragma unroll
        for (int kk = 0; kk < 4; kk++) {
            float lo, hi; unpk2(lo, hi, u2[j][kk]);
            int k0 = 2 * kk, k1 = 2 * kk + 1;
            int d0 = (k0 < 4) ? (4 * sub + k0) : (32 + 4 * sub + k0 - 4);
            int d1 = (k1 < 4) ? (4 * sub + k1) : (32 + 4 * sub + k1 - 4);
            s_part[(pg * 4 + h) * 64 + d0] = lo;
            s_part[(pg * 4 + h) * 64 + d1] = hi;
        }
    }
    __syncthreads();
    {
        const int h = t >> 6, d = t & 63;
        float U = 0.f;
#pragma unroll
        for (int p = 0; p < 32; p++) U += s_part[(p * 4 + h) * 64 + d];
        float L = 0.f;
#pragma unroll
        for (int p = 0; p < 32; p++) L += s_pl[p * 4 + h];
        s_wvec[h * 64 + d] = U / L;
    }
    __syncthreads();

    if (t < Dv) {
        float acc = bv[t];
        const int h = t >> 4;
        const float* wr = wv + t * Dv;
#pragma unroll
        for (int j = 0; j < Dv; j++) acc += __ldg(wr + j) * s_wvec[h * 64 + j];
        s_ctx[t] = acc;
    }
    __syncthreads();
    if (t < Dv) {
        float acc = bo[t];
        const float* wr = wo + t * Dv;
#pragma unroll
        for (int j = 0; j < Dv; j++) acc += __ldg(wr + j) * s_ctx[j];
        s_val[t] = acc;
    }
    __syncthreads();
    if (t < 128) {
        float acc = b_a1[t];
        const float* wr = w_a1 + t * Dv;
#pragma unroll
        for (int j = 0; j < Dv; j++) acc += __ldg(wr + j) * s_val[j];
        g_hbuf[(size_t)b * 128 + t] = fmaxf(acc, 0.f);
    }
    if (t >= 128 && t < 128 + Dv) {
        const int o = t - 128;
        float acc = b_write[o];
        const float* wr = w_write + o * Dv;
#pragma unroll
        for (int j = 0; j < Dv; j++) acc += __ldg(wr + j) * s_val[j];
        g_wvbuf[(size_t)b * Dv + o] = acc;
    }
}

// ---------------------------------------------------------------------------
// K2a (R14): address logits, 8x finer decomposition for L2-latency hiding.
// Grid 1024 = 8 s-tiles x 128 b-tiles; CTA = 8 batches x 256 s-rows; one
// s-row per thread (w_a2 row = 512B contiguous per thread). Writes
// UNNORMALIZED e to g_ebuf and per-(batch,s-tile) partial sums to g_psum.
// ---------------------------------------------------------------------------
__global__ __launch_bounds__(256) void k2a_logits(const float* __restrict__ w_a2,
                                                  const float* __restrict__ b_a2)
{
    const int stile = blockIdx.x & 7;
    const int btile = blockIdx.x >> 3;
    const int b0 = btile * 8;
    const int s = stile * 256 + threadIdx.x;
    const int t = threadIdx.x;
    __shared__ float hs[8 * 128];
    __shared__ float sden[8];

    for (int idx = t; idx < 1024; idx += 256) hs[idx] = g_hbuf[(size_t)b0 * 128 + idx];
    if (t < 8) sden[t] = 0.f;
    __syncthreads();

    float acc[8];
#pragma unroll
    for (int bb = 0; bb < 8; bb++) acc[bb] = 0.f;

    const float4* w4 = (const float4*)w_a2 + (size_t)s * 32;
    const float4* h4 = (const float4*)hs;
#pragma unroll
    for (int k8 = 0; k8 < 16; k8++) {
        float4 wa = __ldg(w4 + 2 * k8);
        float4 wb = __ldg(w4 + 2 * k8 + 1);
#pragma unroll
        for (int bb = 0; bb < 8; bb++) {
            float4 ha = h4[bb * 32 + 2 * k8];
            float4 hb = h4[bb * 32 + 2 * k8 + 1];
            acc[bb] += wa.x * ha.x + wa.y * ha.y + wa.z * ha.z + wa.w * ha.w +
                       wb.x * hb.x + wb.y * hb.y + wb.z * hb.z + wb.w * hb.w;
        }
    }

    const float ba = b_a2[s];
    float e[8];
#pragma unroll
    for (int bb = 0; bb < 8; bb++) {
        e[bb] = __expf(acc[bb] + ba);     // logits small -> safe w/o max-sub
        g_ebuf[(size_t)(b0 + bb) * Sv + s] = e[bb];
    }
#pragma unroll
    for (int off = 16; off; off >>= 1)
#pragma unroll
        for (int bb = 0; bb < 8; bb++)
            e[bb] += __shfl_xor_sync(0xffffffffu, e[bb], off);
    if ((t & 31) == 0) {
#pragma unroll
        for (int bb = 0; bb < 8; bb++) atomicAdd(&sden[bb], e[bb]);
    }
    __syncthreads();
    if (t < 8) g_psum[(b0 + t) * 8 + stile] = sden[t];
}

// K2b: combine the 8 s-tile partials per batch -> 1/denominator.
__global__ __launch_bounds__(256) void k2b_invd()
{
    const int b = blockIdx.x * 256 + threadIdx.x;
    const float* p = &g_psum[b * 8];
    float s = ((p[0] + p[1]) + (p[2] + p[3])) + ((p[4] + p[5]) + (p[6] + p[7]));
    g_invd[b] = 1.f / s;
}

// ---------------------------------------------------------------------------
// K3: out = sp + (write_value - sp) * (e * invd). Streaming, ILP 4.
// REVERSED block order: the tail of sp (last ~100MB streamed by k1) is still
// L2-resident when k3 starts — consume it first for L2 hits.
// ---------------------------------------------------------------------------
__global__ __launch_bounds__(256) void k3_write(const float* __restrict__ sp,
                                                float* __restrict__ out)
{
    const int rb = gridDim.x - 1 - blockIdx.x;                    // reversed
    const size_t base = (size_t)rb * 1024 + threadIdx.x;          // float4 units
#pragma unroll
    for (int j = 0; j < 4; j++) {
        const size_t gi = base + (size_t)j * 256;
        const size_t row = gi >> 4;
        const int b = (int)(row >> 11);
        const float a = __ldg(&g_ebuf[row]) * __ldg(&g_invd[b]);
        const float4 x = __ldcs(((const float4*)sp) + gi);
        const float4 w = __ldg(((const float4*)g_wvbuf) + (size_t)b * 16 + (gi & 15));
        float4 o;
        o.x = x.x + (w.x - x.x) * a;
        o.y = x.y + (w.y - x.y) * a;
        o.z = x.z + (w.z - x.z) * a;
        o.w = x.w + (w.w - x.w) * a;
        __stcs(((float4*)out) + gi, o);
    }
}

extern "C" void kernel_launch(void* const* d_in, const int* in_sizes, int n_in,
                              void* d_out, int out_size)
{
    (void)in_sizes; (void)n_in; (void)out_size;
    const float* query   = (const float*)d_in[0];
    const float* sp      = (const float*)d_in[1];
    const float* wq      = (const float*)d_in[2];
    const float* wk      = (const float*)d_in[3];
    const float* wv      = (const float*)d_in[4];
    const float* bq      = (const float*)d_in[5];
    const float* bk      = (const float*)d_in[6];
    const float* bv      = (const float*)d_in[7];
    const float* wo      = (const float*)d_in[8];
    const float* bo      = (const float*)d_in[9];
    const float* w_write = (const float*)d_in[10];
    const float* b_write = (const float*)d_in[11];
    const float* w_a1    = (const float*)d_in[12];
    const float* b_a1    = (const float*)d_in[13];
    const float* w_a2    = (const float*)d_in[14];
    const float* b_a2    = (const float*)d_in[15];
    float* out = (float*)d_out;

    const int k1_dyn = 8 * NSTAGE * 272 * (int)sizeof(float);   // 104448 bytes
    cudaFuncSetAttribute(k1_attn, cudaFuncAttributeMaxDynamicSharedMemorySize, k1_dyn);

    k1_attn<<<Bv, 256, k1_dyn>>>(query, sp, wq, wk, wv, bq, bk, bv, wo, bo,
                                 w_write, b_write, w_a1, b_a1);
    k2a_logits<<<1024, 256>>>(w_a2, b_a2);
    k2b_invd<<<Bv / 256, 256>>>();
    k3_write<<<(Bv * Sv * Dv / 4) / 1024, 256>>>(sp, out);
}

// round 16
// speedup vs baseline: 2.0036x; 1.0518x over previous
#include <cuda_runtime.h>
#include <math.h>

#define Bv 1024
#define Sv 2048
#define Dv 64
#define Hv 4
#define HDv 16

#define NSTAGE 12      // smem ring stages per warp
#define LOOKAHEAD 8    // chunks in flight

// Scratch (no cudaMalloc allowed) — static device globals.
__device__ float g_hbuf[Bv * 128];        // relu(value @ w_a1.T + b_a1)
__device__ float g_wvbuf[Bv * Dv];        // write_value per batch
__device__ float g_ebuf[(size_t)Bv * Sv]; // NORMALIZED address a[b,s]

__device__ __forceinline__ void cp_async16(void* smem_dst, const void* gsrc) {
    unsigned sd = (unsigned)__cvta_generic_to_shared(smem_dst);
    asm volatile("cp.async.cg.shared.global [%0], [%1], 16;\n"
                 :: "r"(sd), "l"(gsrc) : "memory");
}
#define CP_COMMIT() asm volatile("cp.async.commit_group;\n" ::: "memory")
#define CP_WAIT6()  asm volatile("cp.async.wait_group 6;\n" ::: "memory")
#define CP_WAIT0()  asm volatile("cp.async.wait_group 0;\n" ::: "memory")

// ---- packed f32x2 helpers (sm_103a paired-FP32 pipe) ----
typedef unsigned long long u64t;
__device__ __forceinline__ u64t pk2(float a, float b) {
    u64t r; asm("mov.b64 %0, {%1, %2};" : "=l"(r) : "f"(a), "f"(b)); return r;
}
__device__ __forceinline__ void unpk2(float& a, float& b, u64t p) {
    asm("mov.b64 {%0, %1}, %2;" : "=f"(a), "=f"(b) : "l"(p));
}
__device__ __forceinline__ u64t mul2(u64t a, u64t b) {
    u64t r; asm("mul.rn.f32x2 %0, %1, %2;" : "=l"(r) : "l"(a), "l"(b)); return r;
}
__device__ __forceinline__ void fma2(u64t& d, u64t a, u64t b) {
    asm("fma.rn.f32x2 %0, %1, %2, %0;" : "+l"(d) : "l"(a), "l"(b));
}

// ---- bf16x2 shuffle packing (R12, verified) ----
__device__ __forceinline__ unsigned bpk(float hi, float lo) {
    unsigned r; asm("cvt.rn.bf16x2.f32 %0, %1, %2;" : "=r"(r) : "f"(hi), "f"(lo));
    return r;
}
__device__ __forceinline__ float blo(unsigned p) { return __uint_as_float(p << 16); }
__device__ __forceinline__ float bhi(unsigned p) { return __uint_as_float(p & 0xffff0000u); }

#define LOG2E 1.4426950408889634f

// ---------------------------------------------------------------------------
// K1 (R12 champion, verbatim — 167.8us measured): per-warp cp.async ring,
// unroll-2 interleaved chains, bf16x2-packed shuffle reduction.
// ---------------------------------------------------------------------------
__global__ __launch_bounds__(256, 2) void k1_attn(
    const float* __restrict__ query, const float* __restrict__ sp,
    const float* __restrict__ wq, const float* __restrict__ wk,
    const float* __restrict__ wv, const float* __restrict__ bq,
    const float* __restrict__ bk, const float* __restrict__ bv,
    const float* __restrict__ wo, const float* __restrict__ bo,
    const float* __restrict__ w_write, const float* __restrict__ b_write,
    const float* __restrict__ w_a1, const float* __restrict__ b_a1)
{
    extern __shared__ float dyn[];   // 8 warps * 12 stages * 272 floats (104.4KB)
    __shared__ float s_q[Dv];
    __shared__ float s_qv[Dv];
    __shared__ float s_qk[Hv * Dv];
    __shared__ float s_c[Hv];
    __shared__ float s_pl[32 * Hv];
    __shared__ float s_wvec[Hv * Dv];
    __shared__ float s_ctx[Dv];
    __shared__ float s_val[Dv];

    const int b = blockIdx.x;
    const int t = threadIdx.x;
    const int warp = t >> 5, lane = t & 31;
    const int g = lane >> 3, sub = lane & 7;
    const float* spb = sp + (size_t)b * Sv * Dv;

    float* wbase = dyn + warp * (NSTAGE * 272);     // this warp's private ring
    float* lbase = wbase + g * 68 + sub * 4;        // lane's write slot (per stage)
    const float* src0 = spb + ((size_t)warp * 256 + g) * 64 + sub * 4;

#pragma unroll
    for (int c = 0; c < LOOKAHEAD; c++) {
        float* dst = lbase + c * 272;
        const float* src = src0 + (size_t)c * 256;
        cp_async16(dst, src);
        cp_async16(dst + 32, src + 32);
        CP_COMMIT();
    }

    if (t < Dv) s_q[t] = query[(size_t)b * Dv + t];
    __syncthreads();
    if (t < Dv) {
        float acc = bq[t];
        const float* wr = wq + t * Dv;
#pragma unroll
        for (int j = 0; j < Dv; j++) acc += __ldg(wr + j) * s_q[j];
        s_qv[t] = acc;
    }
    __syncthreads();

    {
        const int h = t >> 6, j = t & 63;
        float acc = 0.f;
#pragma unroll
        for (int tt = 0; tt < HDv; tt++)
            acc += s_qv[h * HDv + tt] * __ldg(&wk[(h * HDv + tt) * Dv + j]);
        s_qk[h * Dv + j] = 0.25f * acc;
        if (t < Hv) {
            float c = 0.f;
#pragma unroll
            for (int tt = 0; tt < HDv; tt++) c += s_qv[t * HDv + tt] * __ldg(&bk[t * HDv + tt]);
            s_c[t] = 0.25f * c;
        }
    }
    __syncthreads();

    u64t qk2[Hv][4];
#pragma unroll
    for (int h = 0; h < Hv; h++) {
        float r[8];
#pragma unroll
        for (int k = 0; k < 8; k++) {
            int d = (k < 4) ? (4 * sub + k) : (32 + 4 * sub + k - 4);
            r[k] = s_qk[h * Dv + d];
        }
#pragma unroll
        for (int kk = 0; kk < 4; kk++) qk2[h][kk] = pk2(r[2 * kk], r[2 * kk + 1]);
    }
    const int base = sub & 3;
    const float cprem = s_c[base] * LOG2E;
    const bool b0 = (sub & 1) != 0;
    const bool b1 = (sub & 2) != 0;

    u64t u2[Hv][4];
    float ls[Hv];
#pragma unroll
    for (int j = 0; j < Hv; j++) {
        ls[j] = 0.f;
#pragma unroll
        for (int kk = 0; kk < 4; kk++) u2[j][kk] = 0ull;
    }

    int st = 0;
    int nst = LOOKAHEAD;
#pragma unroll 1
    for (int c = 0; c < 64; c += 2) {
        CP_WAIT6();

        if (c + 8 < 64) {
            cp_async16(lbase + nst * 272, src0 + (size_t)(c + 8) * 256);
            cp_async16(lbase + nst * 272 + 32, src0 + (size_t)(c + 8) * 256 + 32);
        }
        CP_COMMIT();
        if (c + 9 < 64) {
            cp_async16(lbase + (nst + 1) * 272, src0 + (size_t)(c + 9) * 256);
            cp_async16(lbase + (nst + 1) * 272 + 32, src0 + (size_t)(c + 9) * 256 + 32);
        }
        CP_COMMIT();

        u64t XP[2][4];
#pragma unroll
        for (int j = 0; j < 2; j++) {
            const float4* tp = (const float4*)(wbase + (st + j) * 272);
            float4 a0 = tp[g * 17 + sub];
            float4 a1 = tp[g * 17 + 8 + sub];
            XP[j][0] = pk2(a0.x, a0.y); XP[j][1] = pk2(a0.z, a0.w);
            XP[j][2] = pk2(a1.x, a1.y); XP[j][3] = pk2(a1.z, a1.w);
        }

        float V[2][Hv];
#pragma unroll
        for (int j = 0; j < 2; j++)
#pragma unroll
            for (int h = 0; h < Hv; h++) {
                u64t acc = mul2(qk2[h][0], XP[j][0]);
                fma2(acc, qk2[h][1], XP[j][1]);
                fma2(acc, qk2[h][2], XP[j][2]);
                fma2(acc, qk2[h][3], XP[j][3]);
                float lo, hi; unpk2(lo, hi, acc);
                V[j][h] = lo + hi;
            }

        float a0s[2], a1s[2];
        {
            float s0[2], s1[2];
#pragma unroll
            for (int j = 0; j < 2; j++) {
                s0[j] = b1 ? V[j][0] : V[j][2];
                s1[j] = b1 ? V[j][1] : V[j][3];
            }
            unsigned P0 = bpk(s0[1], s0[0]);
            unsigned P1 = bpk(s1[1], s1[0]);
            unsigned R0 = __shfl_xor_sync(0xffffffffu, P0, 2);
            unsigned R1 = __shfl_xor_sync(0xffffffffu, P1, 2);
            a0s[0] = (b1 ? V[0][2] : V[0][0]) + blo(R0);
            a0s[1] = (b1 ? V[1][2] : V[1][0]) + bhi(R0);
            a1s[0] = (b1 ? V[0][3] : V[0][1]) + blo(R1);
            a1s[1] = (b1 ? V[1][3] : V[1][1]) + bhi(R1);
        }
        float S[2];
        {
            float s2[2];
#pragma unroll
            for (int j = 0; j < 2; j++) s2[j] = b0 ? a0s[j] : a1s[j];
            unsigned P2 = bpk(s2[1], s2[0]);
            unsigned R2 = __shfl_xor_sync(0xffffffffu, P2, 1);
            S[0] = (b0 ? a1s[0] : a0s[0]) + blo(R2);
            S[1] = (b0 ? a1s[1] : a0s[1]) + bhi(R2);
            unsigned P3 = bpk(S[1], S[0]);
            unsigned R3 = __shfl_xor_sync(0xffffffffu, P3, 4);
            S[0] += blo(R3);
            S[1] += bhi(R3);
        }

        float Q[2][4];
        {
            float q0[2];
#pragma unroll
            for (int j = 0; j < 2; j++) q0[j] = exp2f(__fmaf_rn(S[j], LOG2E, cprem));
            unsigned Q0p = bpk(q0[1], q0[0]);
            unsigned Q1p = __shfl_xor_sync(0xffffffffu, Q0p, 1);
            unsigned Q2p = __shfl_xor_sync(0xffffffffu, Q0p, 2);
            unsigned Q3p = __shfl_xor_sync(0xffffffffu, Q1p, 2);
            Q[0][0] = q0[0];     Q[1][0] = q0[1];
            Q[0][1] = blo(Q1p);  Q[1][1] = bhi(Q1p);
            Q[0][2] = blo(Q2p);  Q[1][2] = bhi(Q2p);
            Q[0][3] = blo(Q3p);  Q[1][3] = bhi(Q3p);
        }

#pragma unroll
        for (int j = 0; j < 2; j++) {
#pragma unroll
            for (int hh = 0; hh < Hv; hh++) {
                ls[hh] += Q[j][hh];
                u64t qq = pk2(Q[j][hh], Q[j][hh]);
                fma2(u2[hh][0], qq, XP[j][0]);
                fma2(u2[hh][1], qq, XP[j][1]);
                fma2(u2[hh][2], qq, XP[j][2]);
                fma2(u2[hh][3], qq, XP[j][3]);
            }
        }

        st += 2;  if (st >= NSTAGE) st -= NSTAGE;
        nst += 2; if (nst >= NSTAGE) nst -= NSTAGE;
    }
    CP_WAIT0();
    __syncthreads();

    float* s_part = dyn;
    const int pg = warp * 4 + g;
    if (sub == 0) {
#pragma unroll
        for (int j = 0; j < Hv; j++) s_pl[pg * 4 + j] = ls[j];
    }
#pragma unroll
    for (int j = 0; j < Hv; j++) {
        const int h = base ^ j;
#pragma unroll
        for (int kk = 0; kk < 4; kk++) {
            float lo, hi; unpk2(lo, hi, u2[j][kk]);
            int k0 = 2 * kk, k1 = 2 * kk + 1;
            int d0 = (k0 < 4) ? (4 * sub + k0) : (32 + 4 * sub + k0 - 4);
            int d1 = (k1 < 4) ? (4 * sub + k1) : (32 + 4 * sub + k1 - 4);
            s_part[(pg * 4 + h) * 64 + d0] = lo;
            s_part[(pg * 4 + h) * 64 + d1] = hi;
        }
    }
    __syncthreads();
    {
        const int h = t >> 6, d = t & 63;
        float U = 0.f;
#pragma unroll
        for (int p = 0; p < 32; p++) U += s_part[(p * 4 + h) * 64 + d];
        float L = 0.f;
#pragma unroll
        for (int p = 0; p < 32; p++) L += s_pl[p * 4 + h];
        s_wvec[h * 64 + d] = U / L;
    }
    __syncthreads();

    if (t < Dv) {
        float acc = bv[t];
        const int h = t >> 4;
        const float* wr = wv + t * Dv;
#pragma unroll
        for (int j = 0; j < Dv; j++) acc += __ldg(wr + j) * s_wvec[h * 64 + j];
        s_ctx[t] = acc;
    }
    __syncthreads();
    if (t < Dv) {
        float acc = bo[t];
        const float* wr = wo + t * Dv;
#pragma unroll
        for (int j = 0; j < Dv; j++) acc += __ldg(wr + j) * s_ctx[j];
        s_val[t] = acc;
    }
    __syncthreads();
    if (t < 128) {
        float acc = b_a1[t];
        const float* wr = w_a1 + t * Dv;
#pragma unroll
        for (int j = 0; j < Dv; j++) acc += __ldg(wr + j) * s_val[j];
        g_hbuf[(size_t)b * 128 + t] = fmaxf(acc, 0.f);
    }
    if (t >= 128 && t < 128 + Dv) {
        const int o = t - 128;
        float acc = b_write[o];
        const float* wr = w_write + o * Dv;
#pragma unroll
        for (int j = 0; j < Dv; j++) acc += __ldg(wr + j) * s_val[j];
        g_wvbuf[(size_t)b * Dv + o] = acc;
    }
}

// ---------------------------------------------------------------------------
// K2 (R15): same 8-row x 8-batch register tile as the R12 version (which
// measured ~45us) but 512 THREADS per CTA — thread owns rows t+512r (r<4).
// Same 128MB w_a2 L2 traffic, same internal normalization (no extra kernel),
// but 2.3x the warps per SM to hide the 512B-stride L2 latency.
// ---------------------------------------------------------------------------
__global__ __launch_bounds__(512) void k2_addr(const float* __restrict__ w_a2,
                                               const float* __restrict__ b_a2)
{
    const int b0 = blockIdx.x * 8;
    const int t = threadIdx.x;                 // 0..511
    __shared__ float hs[8 * 128];
    __shared__ float sden[8];

    for (int idx = t; idx < 1024; idx += 512) hs[idx] = g_hbuf[(size_t)b0 * 128 + idx];
    if (t < 8) sden[t] = 0.f;
    __syncthreads();

    float acc[4][8];
#pragma unroll
    for (int r = 0; r < 4; r++)
#pragma unroll
        for (int bb = 0; bb < 8; bb++) acc[r][bb] = 0.f;

    const float4* w4 = (const float4*)w_a2;
    const float4* h4 = (const float4*)hs;
#pragma unroll 1
    for (int k8 = 0; k8 < 16; k8++) {
        float4 ha[8], hb[8];
#pragma unroll
        for (int bb = 0; bb < 8; bb++) {
            ha[bb] = h4[bb * 32 + 2 * k8];
            hb[bb] = h4[bb * 32 + 2 * k8 + 1];
        }
#pragma unroll
        for (int r = 0; r < 4; r++) {
            const int s = t + 512 * r;
            float4 wa = __ldg(w4 + (size_t)s * 32 + 2 * k8);
            float4 wb = __ldg(w4 + (size_t)s * 32 + 2 * k8 + 1);
#pragma unroll
            for (int bb = 0; bb < 8; bb++) {
                acc[r][bb] += wa.x * ha[bb].x + wa.y * ha[bb].y +
                              wa.z * ha[bb].z + wa.w * ha[bb].w +
                              wb.x * hb[bb].x + wb.y * hb[bb].y +
                              wb.z * hb[bb].z + wb.w * hb[bb].w;
            }
        }
    }

    // pass 1: per-batch exp-sum (logits small -> safe without max-sub)
    float psum[8];
#pragma unroll
    for (int bb = 0; bb < 8; bb++) psum[bb] = 0.f;
#pragma unroll
    for (int r = 0; r < 4; r++) {
        const float ba = b_a2[t + 512 * r];
#pragma unroll
        for (int bb = 0; bb < 8; bb++) psum[bb] += __expf(acc[r][bb] + ba);
    }
#pragma unroll
    for (int off = 16; off; off >>= 1)
#pragma unroll
        for (int bb = 0; bb < 8; bb++)
            psum[bb] += __shfl_xor_sync(0xffffffffu, psum[bb], off);
    if ((t & 31) == 0) {
#pragma unroll
        for (int bb = 0; bb < 8; bb++) atomicAdd(&sden[bb], psum[bb]);
    }
    __syncthreads();

    float inv[8];
#pragma unroll
    for (int bb = 0; bb < 8; bb++) inv[bb] = 1.f / sden[bb];

    // pass 2: recompute exp (deterministic), write normalized a
#pragma unroll
    for (int r = 0; r < 4; r++) {
        const int s = t + 512 * r;
        const float ba = b_a2[s];
#pragma unroll
        for (int bb = 0; bb < 8; bb++)
            g_ebuf[(size_t)(b0 + bb) * Sv + s] = __expf(acc[r][bb] + ba) * inv[bb];
    }
}

// ---------------------------------------------------------------------------
// K3 (R12 champion, verbatim): streaming, ILP 4, forward order. ~157us.
// ---------------------------------------------------------------------------
__global__ __launch_bounds__(256) void k3_write(const float* __restrict__ sp,
                                                float* __restrict__ out)
{
    const size_t base = (size_t)blockIdx.x * 1024 + threadIdx.x;  // float4 units
#pragma unroll
    for (int j = 0; j < 4; j++) {
        const size_t gi = base + (size_t)j * 256;
        const size_t row = gi >> 4;
        const int b = (int)(row >> 11);
        const float a = __ldg(&g_ebuf[row]);
        const float4 x = __ldcs(((const float4*)sp) + gi);
        const float4 w = __ldg(((const float4*)g_wvbuf) + (size_t)b * 16 + (gi & 15));
        float4 o;
        o.x = x.x + (w.x - x.x) * a;
        o.y = x.y + (w.y - x.y) * a;
        o.z = x.z + (w.z - x.z) * a;
        o.w = x.w + (w.w - x.w) * a;
        __stcs(((float4*)out) + gi, o);
    }
}

extern "C" void kernel_launch(void* const* d_in, const int* in_sizes, int n_in,
                              void* d_out, int out_size)
{
    (void)in_sizes; (void)n_in; (void)out_size;
    const float* query   = (const float*)d_in[0];
    const float* sp      = (const float*)d_in[1];
    const float* wq      = (const float*)d_in[2];
    const float* wk      = (const float*)d_in[3];
    const float* wv      = (const float*)d_in[4];
    const float* bq      = (const float*)d_in[5];
    const float* bk      = (const float*)d_in[6];
    const float* bv      = (const float*)d_in[7];
    const float* wo      = (const float*)d_in[8];
    const float* bo      = (const float*)d_in[9];
    const float* w_write = (const float*)d_in[10];
    const float* b_write = (const float*)d_in[11];
    const float* w_a1    = (const float*)d_in[12];
    const float* b_a1    = (const float*)d_in[13];
    const float* w_a2    = (const float*)d_in[14];
    const float* b_a2    = (const float*)d_in[15];
    float* out = (float*)d_out;

    const int k1_dyn = 8 * NSTAGE * 272 * (int)sizeof(float);   // 104448 bytes
    cudaFuncSetAttribute(k1_attn, cudaFuncAttributeMaxDynamicSharedMemorySize, k1_dyn);

    k1_attn<<<Bv, 256, k1_dyn>>>(query, sp, wq, wk, wv, bq, bk, bv, wo, bo,
                                 w_write, b_write, w_a1, b_a1);
    k2_addr<<<Bv / 8, 512>>>(w_a2, b_a2);
    k3_write<<<(Bv * Sv * Dv / 4) / 1024, 256>>>(sp, out);
}